// round 1
// baseline (speedup 1.0000x reference)
#include <cuda_runtime.h>
#include <cstdint>
#include <cstddef>

#define DEV __device__ __forceinline__
#define HD __host__ __device__

static constexpr double kPI = 3.14159265358979323846;

// ---------------- constexpr math (compile-time tables) ----------------
HD constexpr double creduce(double x){
  while (x >  kPI) x -= 2.0 * kPI;
  while (x < -kPI) x += 2.0 * kPI;
  return x;
}
HD constexpr double csin(double x){
  x = creduce(x);
  double t = x, s = x, x2 = x * x;
  for (int i = 1; i < 26; ++i){ t *= -x2 / (double)((2*i) * (2*i + 1)); s += t; }
  return s;
}
HD constexpr double ccos(double x){
  x = creduce(x);
  double t = 1.0, s = 1.0, x2 = x * x;
  for (int i = 1; i < 26; ++i){ t *= -x2 / (double)((2*i - 1) * (2*i)); s += t; }
  return s;
}
HD constexpr double clog(double x){
  double r = x, k = 0.0;
  while (r > 1.25) { r *= 0.5; k += 1.0; }
  while (r < 0.75) { r *= 2.0; k -= 1.0; }
  double z = (r - 1.0) / (r + 1.0), z2 = z * z, term = z, s = z;
  for (int i = 1; i < 60; ++i){ term *= z2; s += term / (double)(2*i + 1); }
  return 2.0 * s + k * 0.69314718055994530942;
}

// ---------------- mel filterbank, 2-sparse per spectral bin ----------------
HD constexpr double hz2mel(double f){ return 1127.0 * clog(1.0 + f / 700.0); }
HD constexpr double mel_lo(){ return hz2mel(80.0); }
HD constexpr double mel_step(){ return (hz2mel(7600.0) - hz2mel(80.0)) / 81.0; }
HD constexpr double bin_mel(int k){ return hz2mel(8000.0 * (double)k / 64.0); }

struct MelEnt { int ja; int jb; float wa; float wb; };

// Each bin k (1..64) feeds at most filters i-1 (upper slope) and i (lower slope).
// Window is pre-halved (folds real-split 0.5); bins 32/64 need x2 -> folded here.
HD constexpr MelEnt mel_ent(int k){
  MelEnt e{-1, -1, 0.0f, 0.0f};
  double u = (bin_mel(k) - mel_lo()) / mel_step();
  if (u <= 0.0 || u >= 81.0) return e;
  int i = (int)u;
  double scale = (k == 32 || k == 64) ? 2.0 : 1.0;
  double wu = ((double)(i + 1) - u) * scale;
  double wl = (u - (double)i) * scale;
  if (i - 1 >= 0 && i - 1 <= 79){ e.ja = i - 1; e.wa = (float)wu; }
  if (i <= 79){ e.jb = i; e.wb = (float)wl; }
  return e;
}

// Emission order of bins: pairs (1,63),(2,62),...,(31,33), then 32, then 64.
HD constexpr int emit_bin(int idx){
  if (idx < 62){ int i = idx >> 1; return (idx & 1) ? (63 - i) : (i + 1); }
  return (idx == 62) ? 32 : 64;
}
HD constexpr int targ(int bin, int slot){
  MelEnt e = mel_ent(bin);
  return slot ? e.jb : e.ja;
}
// First writer of a mel register uses '=', later ones '+=' -> no zero-init pass.
HD constexpr bool is_first_touch(int bin, int slot){
  int j = targ(bin, slot);
  if (j < 0) return false;
  int pos = 0;
  for (int idx = 0; idx < 64; ++idx){ if (emit_bin(idx) == bin){ pos = idx; break; } }
  for (int idx = 0; idx < pos; ++idx){
    int b2 = emit_bin(idx);
    if (targ(b2, 0) == j || targ(b2, 1) == j) return false;
  }
  if (slot == 1 && targ(bin, 0) == j) return false;
  return true;
}
HD constexpr bool mel_used(int j){
  for (int idx = 0; idx < 64; ++idx){
    int b2 = emit_bin(idx);
    if (targ(b2, 0) == j || targ(b2, 1) == j) return true;
  }
  return false;
}
HD constexpr int bitrev6(int n){
  int r = 0;
  for (int b = 0; b < 6; ++b) r |= ((n >> b) & 1) << (5 - b);
  return r;
}

// ---------------- magnitude ----------------
DEV float magf(float re, float im){
  float p2 = fmaf(re, re, im * im);
  float m = p2 * rsqrtf(p2);
  return (p2 > 1e-35f) ? m : 0.0f;
}

// ---------------- mel scatter (static register indices) ----------------
template<int BIN>
DEV void scatter(float* mel, float mag){
  constexpr MelEnt e = mel_ent(BIN);
  if constexpr (e.ja >= 0){
    if constexpr (is_first_touch(BIN, 0)) mel[e.ja] = e.wa * mag;
    else mel[e.ja] = fmaf(e.wa, mag, mel[e.ja]);
  }
  if constexpr (e.jb >= 0){
    if constexpr (is_first_touch(BIN, 1)) mel[e.jb] = e.wb * mag;
    else mel[e.jb] = fmaf(e.wb, mag, mel[e.jb]);
  }
}

// ---------------- windowed bit-reversed load (packs real pairs into complex) ----------------
template<int N> struct LoadLoop {
  static DEV void run(float* Ar, float* Ai, const float* sx, int tid){
    constexpr int src = bitrev6(N);
    // pre-halved Hann: 0.5 * (0.5 - 0.5*cos(2*pi*m/128))
    constexpr float w0 = (float)(0.5 * (0.5 - 0.5 * ccos(2.0 * kPI * (double)(2*src)     / 128.0)));
    constexpr float w1 = (float)(0.5 * (0.5 - 0.5 * ccos(2.0 * kPI * (double)(2*src + 1) / 128.0)));
    if constexpr (w0 == 0.0f) Ar[N] = 0.0f;
    else Ar[N] = sx[tid + 2*src] * w0;
    Ai[N] = sx[tid + 2*src + 1] * w1;
    LoadLoop<N + 1>::run(Ar, Ai, sx, tid);
  }
};
template<> struct LoadLoop<64>{ static DEV void run(float*, float*, const float*, int){} };

// ---------------- radix-2 DIT complex FFT-64, fully unrolled, immediate twiddles ----------------
template<int S, int M> struct BflyLoop {
  static DEV void run(float* Ar, float* Ai){
    constexpr int half = 1 << S;
    constexpr int j  = M & (half - 1);
    constexpr int i0 = ((M >> S) << (S + 1)) + j;
    constexpr int i1 = i0 + half;
    float br_ = Ar[i1], bi_ = Ai[i1];
    float tr, ti;
    if constexpr (j == 0){ tr = br_; ti = bi_; }
    else if constexpr (2*j == half){ tr = bi_; ti = -br_; }          // w = -i
    else {
      constexpr float c = (float)ccos(kPI * (double)j / (double)half);
      constexpr float s = (float)csin(kPI * (double)j / (double)half);
      // w = e^{-i*pi*j/half} = (c, -s)
      tr = fmaf(c, br_,  s * bi_);
      ti = fmaf(c, bi_, -(s * br_));
    }
    float ar_ = Ar[i0], ai_ = Ai[i0];
    Ar[i0] = ar_ + tr; Ai[i0] = ai_ + ti;
    Ar[i1] = ar_ - tr; Ai[i1] = ai_ - ti;
    BflyLoop<S, M + 1>::run(Ar, Ai);
  }
};
template<int S> struct BflyLoop<S, 32>{ static DEV void run(float*, float*){} };
template<int S> struct StageLoop {
  static DEV void run(float* Ar, float* Ai){
    BflyLoop<S, 0>::run(Ar, Ai);
    StageLoop<S + 1>::run(Ar, Ai);
  }
};
template<> struct StageLoop<6>{ static DEV void run(float*, float*){} };

// ---------------- real-split + magnitude + mel scatter, per conjugate pair ----------------
template<int K>
DEV void do_pair(float* Ar, float* Ai, float* mel){
  float P = Ar[K],      Q = Ai[K];
  float R = Ar[64 - K], S = Ai[64 - K];
  float zer = P + R, zei = Q - S;
  float zor = Q + S, zoi = R - P;
  constexpr float c = (float)ccos(kPI * (double)K / 64.0);
  constexpr float s = (float)csin(kPI * (double)K / 64.0);
  float A  = fmaf(c, zor,  s * zoi);
  float Bv = fmaf(c, zoi, -(s * zor));
  scatter<K>     (mel, magf(zer + A, zei + Bv));
  scatter<64 - K>(mel, magf(zer - A, Bv - zei));
}
template<int K> struct Pairs {
  static DEV void run(float* Ar, float* Ai, float* mel){
    do_pair<K>(Ar, Ai, mel);
    Pairs<K + 1>::run(Ar, Ai, mel);
  }
};
template<> struct Pairs<32>{ static DEV void run(float*, float*, float*){} };

// ---------------- store mel row to SMEM (untouched bins -> literal 0) ----------------
template<int J> struct StoreLoop {
  static DEV void run(float* dst, const float* mel){
    if constexpr (mel_used(J)) dst[J] = mel[J];
    else dst[J] = 0.0f;
    StoreLoop<J + 1>::run(dst, mel);
  }
};
template<> struct StoreLoop<80>{ static DEV void run(float*, const float*){} };

// ---------------- kernel ----------------
static constexpr int TPB = 128;       // one thread = one frame
static constexpr int NCOL = 81;       // 1 raw sample + 80 mel

__global__ void __launch_bounds__(TPB)
mel_kernel(const float* __restrict__ x, float* __restrict__ out){
  __shared__ float sx[TPB + 128];                 // 255 staged samples
  __shared__ __align__(16) float sout[TPB * NCOL];

  const int tid = threadIdx.x;
  const int t0  = blockIdx.x * TPB;
  const float* xrow = x + (size_t)blockIdx.y * 16384;

  #pragma unroll
  for (int i = tid; i < TPB + 127; i += TPB){
    int t = t0 + i;
    sx[i] = (t < 16384) ? xrow[t] : 0.0f;
  }
  __syncthreads();

  float Ar[64], Ai[64], mel[80];
  LoadLoop<0>::run(Ar, Ai, sx, tid);
  StageLoop<0>::run(Ar, Ai);
  Pairs<1>::run(Ar, Ai, mel);
  scatter<32>(mel, magf(Ar[32], Ai[32]));         // X[32] = (Zr, -Zi), x2 folded into weights
  // bin 64 (f=8kHz) lies above 7600 Hz -> mel_ent(64) empty; scatter is a no-op.
  scatter<64>(mel, fabsf(Ar[0] - Ai[0]));

  // stage 81-float output row in SMEM (stride 81 -> bank-conflict-free)
  sout[tid * NCOL] = sx[tid];
  StoreLoop<0>::run(sout + tid * NCOL + 1, mel);
  __syncthreads();

  // coalesced float4 copy: block region is contiguous & 16B-aligned (t0 % 4 == 0)
  float4* g4 = (float4*)(out + ((size_t)blockIdx.y * 16384 + (size_t)t0) * NCOL);
  const float4* s4 = (const float4*)sout;
  for (int i = tid; i < (TPB * NCOL) / 4; i += TPB) g4[i] = s4[i];
}

extern "C" void kernel_launch(void* const* d_in, const int* in_sizes, int n_in,
                              void* d_out, int out_size){
  (void)in_sizes; (void)n_in; (void)out_size;
  const float* x = (const float*)d_in[0];
  float* out = (float*)d_out;
  dim3 grid(16384 / TPB, 16);
  mel_kernel<<<grid, TPB>>>(x, out);
}

// round 2
// speedup vs baseline: 1.1317x; 1.1317x over previous
#include <cuda_runtime.h>
#include <cstdint>
#include <cstddef>

#define DEV __device__ __forceinline__
#define HD __host__ __device__

static constexpr double kPI = 3.14159265358979323846;

// ---------------- constexpr math (compile-time tables) ----------------
HD constexpr double creduce(double x){
  while (x >  kPI) x -= 2.0 * kPI;
  while (x < -kPI) x += 2.0 * kPI;
  return x;
}
HD constexpr double csin(double x){
  x = creduce(x);
  double t = x, s = x, x2 = x * x;
  for (int i = 1; i < 26; ++i){ t *= -x2 / (double)((2*i) * (2*i + 1)); s += t; }
  return s;
}
HD constexpr double ccos(double x){
  x = creduce(x);
  double t = 1.0, s = 1.0, x2 = x * x;
  for (int i = 1; i < 26; ++i){ t *= -x2 / (double)((2*i - 1) * (2*i)); s += t; }
  return s;
}
HD constexpr double clog(double x){
  double r = x, k = 0.0;
  while (r > 1.25) { r *= 0.5; k += 1.0; }
  while (r < 0.75) { r *= 2.0; k -= 1.0; }
  double z = (r - 1.0) / (r + 1.0), z2 = z * z, term = z, s = z;
  for (int i = 1; i < 60; ++i){ term *= z2; s += term / (double)(2*i + 1); }
  return 2.0 * s + k * 0.69314718055994530942;
}

// ---------------- mel filterbank, 2-sparse per spectral bin ----------------
HD constexpr double hz2mel(double f){ return 1127.0 * clog(1.0 + f / 700.0); }
HD constexpr double mel_lo(){ return hz2mel(80.0); }
HD constexpr double mel_step(){ return (hz2mel(7600.0) - hz2mel(80.0)) / 81.0; }
HD constexpr double bin_mel(int k){ return hz2mel(8000.0 * (double)k / 64.0); }

struct MelEnt { int ja; int jb; float wa; float wb; };

// Each bin k (1..64) feeds at most filters i-1 (upper slope) and i (lower slope).
// Window is pre-halved (folds real-split 0.5); bins 32/64 need x2 -> folded here.
HD constexpr MelEnt mel_ent(int k){
  MelEnt e{-1, -1, 0.0f, 0.0f};
  double u = (bin_mel(k) - mel_lo()) / mel_step();
  if (u <= 0.0 || u >= 81.0) return e;
  int i = (int)u;
  double scale = (k == 32 || k == 64) ? 2.0 : 1.0;
  double wu = ((double)(i + 1) - u) * scale;
  double wl = (u - (double)i) * scale;
  if (i - 1 >= 0 && i - 1 <= 79){ e.ja = i - 1; e.wa = (float)wu; }
  if (i <= 79){ e.jb = i; e.wb = (float)wl; }
  return e;
}

// Emission order of bins: pairs (1,63),(2,62),...,(31,33), then 32, then 64.
HD constexpr int emit_bin(int idx){
  if (idx < 62){ int i = idx >> 1; return (idx & 1) ? (63 - i) : (i + 1); }
  return (idx == 62) ? 32 : 64;
}
HD constexpr int targ(int bin, int slot){
  MelEnt e = mel_ent(bin);
  return slot ? e.jb : e.ja;
}
// First writer of a mel register uses '=', later ones '+=' -> no zero-init pass.
HD constexpr bool is_first_touch(int bin, int slot){
  int j = targ(bin, slot);
  if (j < 0) return false;
  int pos = 0;
  for (int idx = 0; idx < 64; ++idx){ if (emit_bin(idx) == bin){ pos = idx; break; } }
  for (int idx = 0; idx < pos; ++idx){
    int b2 = emit_bin(idx);
    if (targ(b2, 0) == j || targ(b2, 1) == j) return false;
  }
  if (slot == 1 && targ(bin, 0) == j) return false;
  return true;
}
HD constexpr bool mel_used(int j){
  for (int idx = 0; idx < 64; ++idx){
    int b2 = emit_bin(idx);
    if (targ(b2, 0) == j || targ(b2, 1) == j) return true;
  }
  return false;
}
HD constexpr int bitrev6(int n){
  int r = 0;
  for (int b = 0; b < 6; ++b) r |= ((n >> b) & 1) << (5 - b);
  return r;
}

// pre-halved Hann window: 0.5 * (0.5 - 0.5*cos(2*pi*m/128))
HD constexpr float hwin(int m){
  return (float)(0.5 * (0.5 - 0.5 * ccos(2.0 * kPI * (double)m / 128.0)));
}

// ---------------- magnitude: MUFU.SQRT, floor guard via FMNMX ----------------
DEV float magf(float re, float im){
  float p2 = fmaf(re, re, im * im);
  p2 = fmaxf(p2, 1e-37f);
  float m;
  asm("sqrt.approx.f32 %0, %1;" : "=f"(m) : "f"(p2));
  return m;
}

// ---------------- mel scatter (static register indices) ----------------
template<int BIN>
DEV void scatter(float* mel, float mag){
  constexpr MelEnt e = mel_ent(BIN);
  if constexpr (e.ja >= 0){
    if constexpr (is_first_touch(BIN, 0)) mel[e.ja] = e.wa * mag;
    else mel[e.ja] = fmaf(e.wa, mag, mel[e.ja]);
  }
  if constexpr (e.jb >= 0){
    if constexpr (is_first_touch(BIN, 1)) mel[e.jb] = e.wb * mag;
    else mel[e.jb] = fmaf(e.wb, mag, mel[e.jb]);
  }
}

// ---------------- fused window + bit-reversed load + stage-0 butterfly ----------------
// Elements 2M, 2M+1 (bit-reversed srcs s0, s1 = s0 + 32); stage-0 has no twiddle:
//   out0 = e0 + e1, out1 = e0 - e1, with e = (x_even * w_even, x_odd * w_odd).
// Per float lane: t = x1*w1; out0 = fma(x0, w0, t); out1 = fma(x0, w0, -t)  -> 3 ops.
template<int M> struct Fused0 {
  static DEV void run(float* Ar, float* Ai, const float* sx, int tid){
    constexpr int s0 = bitrev6(2*M);
    constexpr int s1 = bitrev6(2*M + 1);          // = s0 + 32
    constexpr float w0r = hwin(2*s0), w0i = hwin(2*s0 + 1);
    constexpr float w1r = hwin(2*s1), w1i = hwin(2*s1 + 1);
    float x0r = sx[tid + 2*s0], x0i = sx[tid + 2*s0 + 1];
    float x1r = sx[tid + 2*s1], x1i = sx[tid + 2*s1 + 1];
    float tr = x1r * w1r;
    float ti = x1i * w1i;
    if constexpr (w0r == 0.0f){                   // only s0 == 0 (window zero at m=0)
      Ar[2*M]     = tr;
      Ar[2*M + 1] = -tr;
    } else {
      Ar[2*M]     = fmaf(x0r, w0r,  tr);
      Ar[2*M + 1] = fmaf(x0r, w0r, -tr);
    }
    Ai[2*M]     = fmaf(x0i, w0i,  ti);
    Ai[2*M + 1] = fmaf(x0i, w0i, -ti);
    Fused0<M + 1>::run(Ar, Ai, sx, tid);
  }
};
template<> struct Fused0<32>{ static DEV void run(float*, float*, const float*, int){} };

// ---------------- radix-2 DIT complex FFT-64, fully unrolled, immediate twiddles ----------------
template<int S, int M> struct BflyLoop {
  static DEV void run(float* Ar, float* Ai){
    constexpr int half = 1 << S;
    constexpr int j  = M & (half - 1);
    constexpr int i0 = ((M >> S) << (S + 1)) + j;
    constexpr int i1 = i0 + half;
    float br_ = Ar[i1], bi_ = Ai[i1];
    float tr, ti;
    if constexpr (j == 0){ tr = br_; ti = bi_; }
    else if constexpr (2*j == half){ tr = bi_; ti = -br_; }          // w = -i
    else {
      constexpr float c = (float)ccos(kPI * (double)j / (double)half);
      constexpr float s = (float)csin(kPI * (double)j / (double)half);
      // w = e^{-i*pi*j/half} = (c, -s)
      tr = fmaf(c, br_,  s * bi_);
      ti = fmaf(c, bi_, -(s * br_));
    }
    float ar_ = Ar[i0], ai_ = Ai[i0];
    Ar[i0] = ar_ + tr; Ai[i0] = ai_ + ti;
    Ar[i1] = ar_ - tr; Ai[i1] = ai_ - ti;
    BflyLoop<S, M + 1>::run(Ar, Ai);
  }
};
template<int S> struct BflyLoop<S, 32>{ static DEV void run(float*, float*){} };
template<int S> struct StageLoop {
  static DEV void run(float* Ar, float* Ai){
    BflyLoop<S, 0>::run(Ar, Ai);
    StageLoop<S + 1>::run(Ar, Ai);
  }
};
template<> struct StageLoop<6>{ static DEV void run(float*, float*){} };

// ---------------- real-split + magnitude + mel scatter, per conjugate pair ----------------
template<int K>
DEV void do_pair(float* Ar, float* Ai, float* mel){
  float P = Ar[K],      Q = Ai[K];
  float R = Ar[64 - K], S = Ai[64 - K];
  float zer = P + R, zei = Q - S;
  float zor = Q + S, zoi = R - P;
  constexpr float c = (float)ccos(kPI * (double)K / 64.0);
  constexpr float s = (float)csin(kPI * (double)K / 64.0);
  float A  = fmaf(c, zor,  s * zoi);
  float Bv = fmaf(c, zoi, -(s * zor));
  scatter<K>     (mel, magf(zer + A, zei + Bv));
  scatter<64 - K>(mel, magf(zer - A, Bv - zei));
}
template<int K> struct Pairs {
  static DEV void run(float* Ar, float* Ai, float* mel){
    do_pair<K>(Ar, Ai, mel);
    Pairs<K + 1>::run(Ar, Ai, mel);
  }
};
template<> struct Pairs<32>{ static DEV void run(float*, float*, float*){} };

// ---------------- store mel row to SMEM (untouched bins -> literal 0) ----------------
template<int J> struct StoreLoop {
  static DEV void run(float* dst, const float* mel){
    if constexpr (mel_used(J)) dst[J] = mel[J];
    else dst[J] = 0.0f;
    StoreLoop<J + 1>::run(dst, mel);
  }
};
template<> struct StoreLoop<80>{ static DEV void run(float*, const float*){} };

// ---------------- kernel ----------------
static constexpr int TPB = 128;       // one thread = one frame
static constexpr int NCOL = 81;       // 1 raw sample + 80 mel

__global__ void __launch_bounds__(TPB, 4)
mel_kernel(const float* __restrict__ x, float* __restrict__ out){
  __shared__ float sx[TPB + 128];                 // 255 staged samples
  __shared__ __align__(16) float sout[TPB * NCOL];

  const int tid = threadIdx.x;
  const int t0  = blockIdx.x * TPB;
  const float* xrow = x + (size_t)blockIdx.y * 16384;

  #pragma unroll
  for (int i = tid; i < TPB + 127; i += TPB){
    int t = t0 + i;
    sx[i] = (t < 16384) ? xrow[t] : 0.0f;
  }
  __syncthreads();

  float Ar[64], Ai[64], mel[80];
  Fused0<0>::run(Ar, Ai, sx, tid);                // window + bitrev load + stage 0
  StageLoop<1>::run(Ar, Ai);                      // stages 1..5
  Pairs<1>::run(Ar, Ai, mel);
  scatter<32>(mel, magf(Ar[32], Ai[32]));         // X[32] = (Zr, -Zi), x2 folded into weights
  // bin 64 (f=8kHz) lies above 7600 Hz -> mel_ent(64) empty; scatter is a no-op.
  scatter<64>(mel, fabsf(Ar[0] - Ai[0]));

  // stage 81-float output row in SMEM (stride 81 -> bank-conflict-free)
  sout[tid * NCOL] = sx[tid];
  StoreLoop<0>::run(sout + tid * NCOL + 1, mel);
  __syncthreads();

  // coalesced float4 copy: block region is contiguous & 16B-aligned (t0 % 4 == 0)
  float4* g4 = (float4*)(out + ((size_t)blockIdx.y * 16384 + (size_t)t0) * NCOL);
  const float4* s4 = (const float4*)sout;
  for (int i = tid; i < (TPB * NCOL) / 4; i += TPB) g4[i] = s4[i];
}

extern "C" void kernel_launch(void* const* d_in, const int* in_sizes, int n_in,
                              void* d_out, int out_size){
  (void)in_sizes; (void)n_in; (void)out_size;
  const float* x = (const float*)d_in[0];
  float* out = (float*)d_out;
  dim3 grid(16384 / TPB, 16);
  mel_kernel<<<grid, TPB>>>(x, out);
}